// round 13
// baseline (speedup 1.0000x reference)
#include <cuda_runtime.h>
#include <cuda_fp16.h>
#include <math_constants.h>
#include <cstdint>

#define B_    16
#define C_    256
#define HW_   1024
#define NTOK  16384
#define KCODE 8192
#define XQ_SIZE  4194304
#define LOSS_OFF 4194304
#define CODE_OFF 4194305
#define TAU   2e-3f

// A: 64 rows x 512B (256 fp16) + 16 pad = 528B pitch
#define A_PITCH   528
#define A_BYTES   (64 * A_PITCH)             // 33792
// B stage: 256 codes x 64B (32 fp16) + 16 pad = 80B pitch, 3-stage ring
#define B_PITCH   80
#define B_STAGE   (256 * B_PITCH)            // 20480
#define B_OFF     A_BYTES
#define HN_OFF    (A_BYTES + 3 * B_STAGE)    // 95232
#define SMEM_TOTAL (HN_OFF + 2048)           // 97280  (2 CTAs/SM)

// rescore smem: cs[32][260] + xsT[256][33]  (floats) -> 3 CTAs/SM
#define RS_CS_F   (32 * 260)                 // 8320
#define RS_XS_F   (256 * 33)                 // 8448
#define RS_SMEM   ((RS_CS_F + RS_XS_F) * 4)  // 67072

// ---------------- Device scratch ----------------
__device__ __align__(256) __half g_A[NTOK * 256];    // xh per token
__device__ __align__(256) __half g_Bw[KCODE * 256];  // eh per code
__device__ __align__(256) float g_hn[KCODE];
__device__ int    g_code[NTOK];
__device__ int    g_flag[NTOK];
__device__ int    g_qn;
__device__ int    g_queue[NTOK];
__device__ unsigned long long g_best64[NTOK];
__device__ double g_partial[512];

// ---------------- helpers ----------------
__device__ __forceinline__ uint32_t smem_u32(const void* p) {
    uint32_t a;
    asm("{ .reg .u64 t; cvta.to.shared.u64 t, %1; cvt.u32.u64 %0, t; }" : "=r"(a) : "l"(p));
    return a;
}
__device__ __forceinline__ void cp_async16(uint32_t dst, const void* src) {
    asm volatile("cp.async.cg.shared.global [%0], [%1], 16;" :: "r"(dst), "l"(src) : "memory");
}
#define CP_COMMIT() asm volatile("cp.async.commit_group;" ::: "memory")
#define CP_WAIT(n)  asm volatile("cp.async.wait_group %0;" :: "n"(n) : "memory")

__device__ __forceinline__ void ldsm4(uint32_t* r, uint32_t addr) {
    asm volatile("ldmatrix.sync.aligned.m8n8.x4.shared.b16 {%0,%1,%2,%3}, [%4];"
                 : "=r"(r[0]), "=r"(r[1]), "=r"(r[2]), "=r"(r[3]) : "r"(addr));
}
__device__ __forceinline__ void mma_fp16(float* d, const uint32_t* a, const uint32_t* b) {
    asm volatile("mma.sync.aligned.m16n8k16.row.col.f32.f16.f16.f32 "
                 "{%0,%1,%2,%3}, {%4,%5,%6,%7}, {%8,%9}, {%0,%1,%2,%3};"
                 : "+f"(d[0]), "+f"(d[1]), "+f"(d[2]), "+f"(d[3])
                 : "r"(a[0]), "r"(a[1]), "r"(a[2]), "r"(a[3]), "r"(b[0]), "r"(b[1]));
}
__device__ __forceinline__ float f4get(const float4& v, int q) {
    switch (q) { case 0: return v.x; case 1: return v.y; case 2: return v.z; default: return v.w; }
}
__device__ __forceinline__ void upd(float& b, float& s, int& i, float v, int c) {
    if (v > b) { s = b; b = v; i = c; }
    else if (v > s) s = v;
}
// order-preserving (score, idx) pack: higher score wins; ties -> smaller idx.
__device__ __forceinline__ unsigned long long pack_si(float s, int idx) {
    uint32_t u = __float_as_uint(s);
    u = (u & 0x80000000u) ? ~u : (u | 0x80000000u);
    return ((unsigned long long)u << 32) | (uint32_t)(0xFFFFFFFFu - (uint32_t)idx);
}
__device__ __forceinline__ int unpack_idx(unsigned long long k) {
    return (int)(0xFFFFFFFFu - (uint32_t)(k & 0xFFFFFFFFull));
}

// ---------------- Kernel 1: x -> token-major fp16 ----------------
__global__ void vq_prep(const float* __restrict__ x) {
    __shared__ float tile[32][33];
    int c0 = blockIdx.x << 5, hw0 = blockIdx.y << 5, b = blockIdx.z;
    const float* xb = x + (size_t)b * (C_ * HW_);
#pragma unroll
    for (int k = 0; k < 4; ++k)
        tile[threadIdx.y + k * 8][threadIdx.x] =
            xb[(size_t)(c0 + threadIdx.y + k * 8) * HW_ + hw0 + threadIdx.x];
    __syncthreads();
#pragma unroll
    for (int k = 0; k < 4; ++k) {
        int token = b * HW_ + hw0 + threadIdx.y + k * 8;
        int c = c0 + threadIdx.x;
        g_A[(size_t)token * 256 + c] = __float2half_rn(tile[threadIdx.x][threadIdx.y + k * 8]);
    }
}

// ---------------- Kernel 2: w -> fp16 eh + hn + queue reset ----------
__global__ void vq_wprep(const float* __restrict__ w) {
    int k = blockIdx.x, c = threadIdx.x;
    if (k == 0 && c == 0) g_qn = 0;
    float e = w[(size_t)k * C_ + c];
    g_Bw[(size_t)k * 256 + c] = __float2half_rn(e);
    float s = e * e;
#pragma unroll
    for (int off = 16; off > 0; off >>= 1)
        s += __shfl_down_sync(0xffffffffu, s, off);
    __shared__ float ws[8];
    if ((c & 31) == 0) ws[c >> 5] = s;
    __syncthreads();
    if (c == 0) {
        float t = 0.f;
#pragma unroll
        for (int i = 0; i < 8; ++i) t += ws[i];
        g_hn[k] = 0.5f * t;
    }
}

// ---------------- Kernel 3: fp16 HMMA GEMM + fused argmax ----------------
// 256 CTAs x 64 tokens, 2 CTAs/SM. score = xh.eh (err ~2e-4 RMS, TAU=2e-3).
// 256 gstages = 32 chunks (256 codes) x 8 k-slabs (32 k). 3-stage cp.async ring.
__device__ __forceinline__ void issue_stage(uint32_t sb, int slot, int gs, int tid) {
    int ch = gs >> 3, kc = gs & 7;
    const __half* src = g_Bw + (size_t)ch * (256 * 256) + kc * 32;
    uint32_t dst = sb + B_OFF + slot * B_STAGE;
#pragma unroll
    for (int i = 0; i < 4; ++i) {
        int g = i * 256 + tid;          // 1024 granules of 16B (256 codes x 4)
        int code = g >> 2, q = g & 3;
        cp_async16(dst + code * B_PITCH + q * 16, src + (size_t)code * 256 + q * 8);
    }
}

__global__ void __launch_bounds__(256, 2) vq_argmax_mma() {
    extern __shared__ char smem[];
    uint32_t sb = smem_u32(smem);
    int tid = threadIdx.x, lane = tid & 31, wid = tid >> 5;
    int wm = wid >> 2, wn = wid & 3;
    int t0g = blockIdx.x << 6;

    // Prologue: A tile (64x512B) + stage0 + hn(chunk0); then stage1
#pragma unroll
    for (int i = 0; i < 8; ++i) {
        int g = i * 256 + tid;
        int row = g >> 5, q = g & 31;
        cp_async16(sb + row * A_PITCH + q * 16, g_A + (size_t)(t0g + row) * 256 + q * 8);
    }
    issue_stage(sb, 0, 0, tid);
    if (tid < 64) cp_async16(sb + HN_OFF + tid * 16, g_hn + tid * 4);
    CP_COMMIT();
    issue_stage(sb, 1, 1, tid);
    CP_COMMIT();

    uint32_t a_base = sb + (wm * 32 + (lane & 15)) * A_PITCH + (lane >> 4) * 16;
    uint32_t b_base = B_OFF +
        (uint32_t)(wn * 64 + ((lane >> 4) & 1) * 8 + (lane & 7)) * B_PITCH +
        ((lane >> 3) & 1) * 16;

    float tb[4], ts[4]; int tix[4];
#pragma unroll
    for (int k = 0; k < 4; ++k) { tb[k] = -CUDART_INF_F; ts[k] = -CUDART_INF_F; tix[k] = 0x7fffffff; }

    float d[2][8][4];
    int slot = 0;   // gs % 3

    for (int gs = 0; gs < 256; ++gs) {
        int ch = gs >> 3, kc = gs & 7;
        if (kc == 0) {
#pragma unroll
            for (int mt = 0; mt < 2; ++mt)
#pragma unroll
                for (int nt = 0; nt < 8; ++nt)
#pragma unroll
                    for (int q = 0; q < 4; ++q) d[mt][nt][q] = 0.f;
        }

        CP_WAIT(1);
        __syncthreads();
        uint32_t bst = sb + slot * B_STAGE + b_base;
        uint32_t ak = a_base + (uint32_t)(kc * 64);
#pragma unroll
        for (int j = 0; j < 2; ++j) {
            uint32_t ar[2][4];
#pragma unroll
            for (int mt = 0; mt < 2; ++mt)
                ldsm4(ar[mt], ak + mt * (16 * A_PITCH) + j * 32);
            uint32_t br[8][2];
#pragma unroll
            for (int p = 0; p < 4; ++p) {
                uint32_t r[4];
                ldsm4(r, bst + p * (16 * B_PITCH) + j * 32);
                br[2 * p][0] = r[0]; br[2 * p][1] = r[1];
                br[2 * p + 1][0] = r[2]; br[2 * p + 1][1] = r[3];
            }
#pragma unroll
            for (int mt = 0; mt < 2; ++mt)
#pragma unroll
                for (int nt = 0; nt < 8; ++nt)
                    mma_fp16(d[mt][nt], ar[mt], br[nt]);
        }
        // next issue targets slot (gs+2)%3, distinct from slots read at gs, gs+1;
        // the overwritten slot was last read at gs-1, sealed by the barrier above.
        int g2 = gs + 2;
        if (g2 < 256) {
            int slot2 = slot + 2; if (slot2 >= 3) slot2 -= 3;
            issue_stage(sb, slot2, g2, tid);
            if (kc == 0 && tid < 64 && ch + 1 < 32) {
                int ch2 = ch + 1;
                cp_async16(sb + HN_OFF + ((ch2 & 1) << 10) + tid * 16,
                           g_hn + ch2 * 256 + tid * 4);
            }
            CP_COMMIT();
        }

        if (kc == 7) {
            const float* hnc = (const float*)(smem + HN_OFF + ((ch & 1) << 10));
            int n0 = ch * 256 + wn * 64 + (lane & 3) * 2;
            int l0 = wn * 64 + (lane & 3) * 2;
#pragma unroll
            for (int mt = 0; mt < 2; ++mt) {
#pragma unroll
                for (int nt = 0; nt < 8; ++nt) {
                    int c0 = n0 + nt * 8;
                    float2 h = *(const float2*)(hnc + l0 + nt * 8);
                    upd(tb[2 * mt], ts[2 * mt], tix[2 * mt], d[mt][nt][0] - h.x, c0);
                    upd(tb[2 * mt], ts[2 * mt], tix[2 * mt], d[mt][nt][1] - h.y, c0 + 1);
                    upd(tb[2 * mt + 1], ts[2 * mt + 1], tix[2 * mt + 1], d[mt][nt][2] - h.x, c0);
                    upd(tb[2 * mt + 1], ts[2 * mt + 1], tix[2 * mt + 1], d[mt][nt][3] - h.y, c0 + 1);
                }
            }
        }
        if (++slot == 3) slot = 0;
    }

    // merge across the 4 lanes of each quad (different code columns)
#pragma unroll
    for (int k = 0; k < 4; ++k) {
#pragma unroll
        for (int off = 1; off <= 2; off <<= 1) {
            float ob = __shfl_xor_sync(0xffffffffu, tb[k], off);
            float os = __shfl_xor_sync(0xffffffffu, ts[k], off);
            int   oi = __shfl_xor_sync(0xffffffffu, tix[k], off);
            if (ob > tb[k]) { ts[k] = fmaxf(tb[k], os); tb[k] = ob; tix[k] = oi; }
            else if (ob == tb[k]) { ts[k] = tb[k]; if (oi < tix[k]) tix[k] = oi; }
            else { ts[k] = fmaxf(ts[k], ob); }
        }
    }

    __syncthreads();   // done with A/B smem; reuse for reduction
    float* rb = (float*)smem;          // [4][64]
    float* rs = rb + 256;              // [4][64]
    int*   ri = (int*)(rs + 256);      // [4][64]
    if ((lane & 3) == 0) {
#pragma unroll
        for (int k = 0; k < 4; ++k) {
            int tl = wm * 32 + (k >> 1) * 16 + (lane >> 2) + (k & 1) * 8;
            rb[wn * 64 + tl] = tb[k];
            rs[wn * 64 + tl] = ts[k];
            ri[wn * 64 + tl] = tix[k];
        }
    }
    __syncthreads();
    if (tid < 64) {
        float b = rb[tid], s = rs[tid]; int i = ri[tid];
#pragma unroll
        for (int w = 1; w < 4; ++w) {
            float ob = rb[w * 64 + tid], os = rs[w * 64 + tid];
            int oi = ri[w * 64 + tid];
            if (ob > b) { s = fmaxf(b, os); b = ob; i = oi; }
            else if (ob == b) { s = b; if (oi < i) i = oi; }
            else { s = fmaxf(s, ob); }
        }
        int tok = t0g + tid;
        g_code[tok] = i;
        int fl = (b - s < TAU) ? 1 : 0;
        g_flag[tok] = fl;
        if (fl) {
            g_best64[tok] = 0ull;
            int p = atomicAdd(&g_qn, 1);
            g_queue[p] = tok;
        }
    }
}

// ---------------- Kernel 4: throughput rescore (exact fp32 mini-GEMM) -----
// 32-code tiles, 67KB smem -> 3 CTAs/SM. Each warp: 4 codes x 32 tokens.
__global__ void __launch_bounds__(256, 3)
vq_rescore(const float* __restrict__ x, const float* __restrict__ w) {
    extern __shared__ float rsm[];
    float* cs = rsm;                 // [32][260]
    float* xs = rsm + RS_CS_F;       // [256][33]
    int tid = threadIdx.x, lane = tid & 31, wrp = tid >> 5;
    int qn = g_qn;
    if (qn == 0) return;
    if ((int)blockIdx.y * 32 >= qn) return;

    int code0 = blockIdx.x << 5;     // 256 slices of 32 codes
#pragma unroll
    for (int i = 0; i < 8; ++i) {
        int g = i * 256 + tid;       // 2048 float4 granules
        int code = g >> 6, q = g & 63;
        ((float4*)(cs + code * 260))[q] =
            *(const float4*)(w + (size_t)(code0 + code) * 256 + q * 4);
    }
    float hn4[4];
#pragma unroll
    for (int c4 = 0; c4 < 4; ++c4) hn4[c4] = g_hn[code0 + wrp * 4 + c4];

    for (int tile = blockIdx.y; tile * 32 < qn; tile += (int)gridDim.y) {
        int tbase = tile * 32;
        int ntok = min(32, qn - tbase);
        __syncthreads();
#pragma unroll
        for (int i = 0; i < 32; ++i) {
            int g = i * 256 + tid;
            int c = g >> 5, tok = g & 31;
            if (tok < ntok) {
                int t = g_queue[tbase + tok];
                int b = t >> 10, hw = t & 1023;
                xs[c * 33 + tok] = x[((size_t)b * 256 + c) * 1024 + hw];
            }
        }
        __syncthreads();

        int myoff = (lane < ntok) ? lane : 0;
        float acc[4];
#pragma unroll
        for (int c4 = 0; c4 < 4; ++c4) acc[c4] = 0.f;
#pragma unroll
        for (int kc = 0; kc < 16; ++kc) {
            float xr[16];
#pragma unroll
            for (int j = 0; j < 16; ++j) xr[j] = xs[(kc * 16 + j) * 33 + myoff];
#pragma unroll
            for (int c4 = 0; c4 < 4; ++c4) {
                const float4* cr = (const float4*)(cs + (wrp * 4 + c4) * 260 + kc * 16);
#pragma unroll
                for (int v = 0; v < 4; ++v) {
                    float4 cv = cr[v];
                    acc[c4] = fmaf(xr[v * 4 + 0], cv.x, acc[c4]);
                    acc[c4] = fmaf(xr[v * 4 + 1], cv.y, acc[c4]);
                    acc[c4] = fmaf(xr[v * 4 + 2], cv.z, acc[c4]);
                    acc[c4] = fmaf(xr[v * 4 + 3], cv.w, acc[c4]);
                }
            }
        }
        float best = acc[0] - hn4[0]; int bi = code0 + wrp * 4;
#pragma unroll
        for (int c4 = 1; c4 < 4; ++c4) {
            float v = acc[c4] - hn4[c4];
            if (v > best) { best = v; bi = code0 + wrp * 4 + c4; }
        }
        if (lane < ntok) {
            int t = g_queue[tbase + lane];
            atomicMax(&g_best64[t], pack_si(best, bi));
        }
    }
}

// ---------------- Kernel 5: gather x_q + code output + loss partials ------
__global__ void vq_gather(const float* __restrict__ x, const float* __restrict__ w,
                          float* __restrict__ out) {
    int bx = blockIdx.x;
    int b = bx >> 5, hw0 = (bx & 31) << 5;
    int tid = threadIdx.x;
    int hwl = tid & 31, cg = tid >> 5;
    int t = b * HW_ + hw0 + hwl;
    int k;
    if (g_flag[t]) {
        k = unpack_idx(g_best64[t]);
    } else {
        k = g_code[t];
    }
    if (cg == 0) out[CODE_OFF + t] = (float)k;   // code output (token-major == B,H,W)
    const float* e  = w + (size_t)k * C_;
    const float* xb = x + (size_t)b * (C_ * HW_) + hw0 + hwl;
    float* ob = out + (size_t)b * (C_ * HW_) + hw0 + hwl;
    float ls = 0.f;
#pragma unroll
    for (int p = 0; p < 8; ++p) {
        int c0 = ((p << 3) + cg) << 2;
        float4 ev = *(const float4*)(e + c0);
#pragma unroll
        for (int j = 0; j < 4; ++j) {
            int c = c0 + j;
            float v  = f4get(ev, j);
            float xv = xb[(size_t)c * HW_];
            ob[(size_t)c * HW_] = v;
            float dd = v - xv;
            ls += dd * dd;
        }
    }
#pragma unroll
    for (int off = 16; off > 0; off >>= 1)
        ls += __shfl_down_sync(0xffffffffu, ls, off);
    __shared__ float ws[8];
    if ((tid & 31) == 0) ws[tid >> 5] = ls;
    __syncthreads();
    if (tid == 0) {
        float s = 0.f;
#pragma unroll
        for (int i = 0; i < 8; ++i) s += ws[i];
        g_partial[bx] = (double)s;
    }
}

// ---------------- Kernel 6: finalize loss ----------------
__global__ void vq_finalize(float* __restrict__ out) {
    if (threadIdx.x == 0) {
        double s = 0.0;
        for (int i = 0; i < 512; ++i) s += g_partial[i];
        out[LOSS_OFF] = (float)(1.25 * s / (double)XQ_SIZE);
    }
}

// ---------------- Launch ----------------
extern "C" void kernel_launch(void* const* d_in, const int* in_sizes, int n_in,
                              void* d_out, int out_size) {
    const float* x = (const float*)d_in[0];
    const float* w = (const float*)d_in[1];
    float* out = (float*)d_out;

    cudaFuncSetAttribute((const void*)vq_argmax_mma,
                         cudaFuncAttributeMaxDynamicSharedMemorySize, SMEM_TOTAL);
    cudaFuncSetAttribute((const void*)vq_rescore,
                         cudaFuncAttributeMaxDynamicSharedMemorySize, RS_SMEM);

    vq_prep<<<dim3(8, 32, 16), dim3(32, 8)>>>(x);
    vq_wprep<<<KCODE, 256>>>(w);
    vq_argmax_mma<<<256, 256, SMEM_TOTAL>>>();
    vq_rescore<<<dim3(256, 8), 256, RS_SMEM>>>(x, w);
    vq_gather<<<512, 256>>>(x, w, out);
    vq_finalize<<<1, 32>>>(out);
}

// round 14
// speedup vs baseline: 1.2612x; 1.2612x over previous
#include <cuda_runtime.h>
#include <cuda_fp16.h>
#include <math_constants.h>
#include <cstdint>

#define B_    16
#define C_    256
#define HW_   1024
#define NTOK  16384
#define KCODE 8192
#define XQ_SIZE  4194304
#define LOSS_OFF 4194304
#define CODE_OFF 4194305
#define TAU   2e-3f

// A: 64 rows x 512B (256 fp16) + 16 pad = 528B pitch
#define A_PITCH   528
#define A_BYTES   (64 * A_PITCH)             // 33792
// B stage: 256 codes x 64B (32 fp16) + 16 pad = 80B pitch, 3-stage ring
#define B_PITCH   80
#define B_STAGE   (256 * B_PITCH)            // 20480
#define B_OFF     A_BYTES
#define HN_OFF    (A_BYTES + 3 * B_STAGE)    // 95232
#define SMEM_TOTAL (HN_OFF + 2048)           // 97280  (2 CTAs/SM)

// rescore smem: cs[64][260] + xsT[256][33]  (floats)
#define RS_CS_F   (64 * 260)                 // 16640
#define RS_XS_F   (256 * 33)                 // 8448
#define RS_SMEM   ((RS_CS_F + RS_XS_F) * 4)  // 100352

// ---------------- Device scratch ----------------
__device__ __align__(256) __half g_A[NTOK * 256];    // xh per token
__device__ __align__(256) __half g_Bw[KCODE * 256];  // eh per code
__device__ __align__(256) float g_hn[KCODE];
__device__ int    g_code[NTOK];
__device__ int    g_flag[NTOK];
__device__ int    g_qn;
__device__ int    g_queue[NTOK];
__device__ unsigned long long g_best64[NTOK];
__device__ double g_partial[512];

// ---------------- helpers ----------------
__device__ __forceinline__ uint32_t smem_u32(const void* p) {
    uint32_t a;
    asm("{ .reg .u64 t; cvta.to.shared.u64 t, %1; cvt.u32.u64 %0, t; }" : "=r"(a) : "l"(p));
    return a;
}
__device__ __forceinline__ void cp_async16(uint32_t dst, const void* src) {
    asm volatile("cp.async.cg.shared.global [%0], [%1], 16;" :: "r"(dst), "l"(src) : "memory");
}
#define CP_COMMIT() asm volatile("cp.async.commit_group;" ::: "memory")
#define CP_WAIT(n)  asm volatile("cp.async.wait_group %0;" :: "n"(n) : "memory")

__device__ __forceinline__ void ldsm4(uint32_t* r, uint32_t addr) {
    asm volatile("ldmatrix.sync.aligned.m8n8.x4.shared.b16 {%0,%1,%2,%3}, [%4];"
                 : "=r"(r[0]), "=r"(r[1]), "=r"(r[2]), "=r"(r[3]) : "r"(addr));
}
__device__ __forceinline__ void mma_fp16(float* d, const uint32_t* a, const uint32_t* b) {
    asm volatile("mma.sync.aligned.m16n8k16.row.col.f32.f16.f16.f32 "
                 "{%0,%1,%2,%3}, {%4,%5,%6,%7}, {%8,%9}, {%0,%1,%2,%3};"
                 : "+f"(d[0]), "+f"(d[1]), "+f"(d[2]), "+f"(d[3])
                 : "r"(a[0]), "r"(a[1]), "r"(a[2]), "r"(a[3]), "r"(b[0]), "r"(b[1]));
}
__device__ __forceinline__ float f4get(const float4& v, int q) {
    switch (q) { case 0: return v.x; case 1: return v.y; case 2: return v.z; default: return v.w; }
}
__device__ __forceinline__ void upd(float& b, float& s, int& i, float v, int c) {
    if (v > b) { s = b; b = v; i = c; }
    else if (v > s) s = v;
}
// order-preserving (score, idx) pack: higher score wins; ties -> smaller idx.
__device__ __forceinline__ unsigned long long pack_si(float s, int idx) {
    uint32_t u = __float_as_uint(s);
    u = (u & 0x80000000u) ? ~u : (u | 0x80000000u);
    return ((unsigned long long)u << 32) | (uint32_t)(0xFFFFFFFFu - (uint32_t)idx);
}
__device__ __forceinline__ int unpack_idx(unsigned long long k) {
    return (int)(0xFFFFFFFFu - (uint32_t)(k & 0xFFFFFFFFull));
}

// ---------------- Kernel 1: x -> token-major fp16 ----------------
__global__ void vq_prep(const float* __restrict__ x) {
    __shared__ float tile[32][33];
    int c0 = blockIdx.x << 5, hw0 = blockIdx.y << 5, b = blockIdx.z;
    const float* xb = x + (size_t)b * (C_ * HW_);
#pragma unroll
    for (int k = 0; k < 4; ++k)
        tile[threadIdx.y + k * 8][threadIdx.x] =
            xb[(size_t)(c0 + threadIdx.y + k * 8) * HW_ + hw0 + threadIdx.x];
    __syncthreads();
#pragma unroll
    for (int k = 0; k < 4; ++k) {
        int token = b * HW_ + hw0 + threadIdx.y + k * 8;
        int c = c0 + threadIdx.x;
        g_A[(size_t)token * 256 + c] = __float2half_rn(tile[threadIdx.x][threadIdx.y + k * 8]);
    }
}

// ---------------- Kernel 2: w -> fp16 eh + hn + queue reset ----------
__global__ void vq_wprep(const float* __restrict__ w) {
    int k = blockIdx.x, c = threadIdx.x;
    if (k == 0 && c == 0) g_qn = 0;
    float e = w[(size_t)k * C_ + c];
    g_Bw[(size_t)k * 256 + c] = __float2half_rn(e);
    float s = e * e;
#pragma unroll
    for (int off = 16; off > 0; off >>= 1)
        s += __shfl_down_sync(0xffffffffu, s, off);
    __shared__ float ws[8];
    if ((c & 31) == 0) ws[c >> 5] = s;
    __syncthreads();
    if (c == 0) {
        float t = 0.f;
#pragma unroll
        for (int i = 0; i < 8; ++i) t += ws[i];
        g_hn[k] = 0.5f * t;
    }
}

// ---------------- Kernel 3: fp16 HMMA GEMM + fused argmax ----------------
// 256 CTAs x 64 tokens, 2 CTAs/SM. score = xh.eh (err ~2e-4 RMS, TAU=2e-3).
// 256 gstages = 32 chunks (256 codes) x 8 k-slabs (32 k). 3-stage cp.async ring.
__device__ __forceinline__ void issue_stage(uint32_t sb, int slot, int gs, int tid) {
    int ch = gs >> 3, kc = gs & 7;
    const __half* src = g_Bw + (size_t)ch * (256 * 256) + kc * 32;
    uint32_t dst = sb + B_OFF + slot * B_STAGE;
#pragma unroll
    for (int i = 0; i < 4; ++i) {
        int g = i * 256 + tid;          // 1024 granules of 16B (256 codes x 4)
        int code = g >> 2, q = g & 3;
        cp_async16(dst + code * B_PITCH + q * 16, src + (size_t)code * 256 + q * 8);
    }
}

__global__ void __launch_bounds__(256, 2) vq_argmax_mma() {
    extern __shared__ char smem[];
    uint32_t sb = smem_u32(smem);
    int tid = threadIdx.x, lane = tid & 31, wid = tid >> 5;
    int wm = wid >> 2, wn = wid & 3;
    int t0g = blockIdx.x << 6;

    // Prologue: A tile (64x512B) + stage0 + hn(chunk0); then stage1
#pragma unroll
    for (int i = 0; i < 8; ++i) {
        int g = i * 256 + tid;
        int row = g >> 5, q = g & 31;
        cp_async16(sb + row * A_PITCH + q * 16, g_A + (size_t)(t0g + row) * 256 + q * 8);
    }
    issue_stage(sb, 0, 0, tid);
    if (tid < 64) cp_async16(sb + HN_OFF + tid * 16, g_hn + tid * 4);
    CP_COMMIT();
    issue_stage(sb, 1, 1, tid);
    CP_COMMIT();

    uint32_t a_base = sb + (wm * 32 + (lane & 15)) * A_PITCH + (lane >> 4) * 16;
    uint32_t b_base = B_OFF +
        (uint32_t)(wn * 64 + ((lane >> 4) & 1) * 8 + (lane & 7)) * B_PITCH +
        ((lane >> 3) & 1) * 16;

    float tb[4], ts[4]; int tix[4];
#pragma unroll
    for (int k = 0; k < 4; ++k) { tb[k] = -CUDART_INF_F; ts[k] = -CUDART_INF_F; tix[k] = 0x7fffffff; }

    float d[2][8][4];
    int slot = 0;   // gs % 3

    for (int gs = 0; gs < 256; ++gs) {
        int ch = gs >> 3, kc = gs & 7;
        if (kc == 0) {
#pragma unroll
            for (int mt = 0; mt < 2; ++mt)
#pragma unroll
                for (int nt = 0; nt < 8; ++nt)
#pragma unroll
                    for (int q = 0; q < 4; ++q) d[mt][nt][q] = 0.f;
        }

        CP_WAIT(1);
        __syncthreads();
        uint32_t bst = sb + slot * B_STAGE + b_base;
        uint32_t ak = a_base + (uint32_t)(kc * 64);
#pragma unroll
        for (int j = 0; j < 2; ++j) {
            uint32_t ar[2][4];
#pragma unroll
            for (int mt = 0; mt < 2; ++mt)
                ldsm4(ar[mt], ak + mt * (16 * A_PITCH) + j * 32);
            uint32_t br[8][2];
#pragma unroll
            for (int p = 0; p < 4; ++p) {
                uint32_t r[4];
                ldsm4(r, bst + p * (16 * B_PITCH) + j * 32);
                br[2 * p][0] = r[0]; br[2 * p][1] = r[1];
                br[2 * p + 1][0] = r[2]; br[2 * p + 1][1] = r[3];
            }
#pragma unroll
            for (int mt = 0; mt < 2; ++mt)
#pragma unroll
                for (int nt = 0; nt < 8; ++nt)
                    mma_fp16(d[mt][nt], ar[mt], br[nt]);
        }
        // next issue targets slot (gs+2)%3, distinct from slots read at gs, gs+1;
        // the overwritten slot was last read at gs-1, sealed by the barrier above.
        int g2 = gs + 2;
        if (g2 < 256) {
            int slot2 = slot + 2; if (slot2 >= 3) slot2 -= 3;
            issue_stage(sb, slot2, g2, tid);
            if (kc == 0 && tid < 64 && ch + 1 < 32) {
                int ch2 = ch + 1;
                cp_async16(sb + HN_OFF + ((ch2 & 1) << 10) + tid * 16,
                           g_hn + ch2 * 256 + tid * 4);
            }
            CP_COMMIT();
        }

        if (kc == 7) {
            const float* hnc = (const float*)(smem + HN_OFF + ((ch & 1) << 10));
            int n0 = ch * 256 + wn * 64 + (lane & 3) * 2;
            int l0 = wn * 64 + (lane & 3) * 2;
#pragma unroll
            for (int mt = 0; mt < 2; ++mt) {
#pragma unroll
                for (int nt = 0; nt < 8; ++nt) {
                    int c0 = n0 + nt * 8;
                    float2 h = *(const float2*)(hnc + l0 + nt * 8);
                    upd(tb[2 * mt], ts[2 * mt], tix[2 * mt], d[mt][nt][0] - h.x, c0);
                    upd(tb[2 * mt], ts[2 * mt], tix[2 * mt], d[mt][nt][1] - h.y, c0 + 1);
                    upd(tb[2 * mt + 1], ts[2 * mt + 1], tix[2 * mt + 1], d[mt][nt][2] - h.x, c0);
                    upd(tb[2 * mt + 1], ts[2 * mt + 1], tix[2 * mt + 1], d[mt][nt][3] - h.y, c0 + 1);
                }
            }
        }
        if (++slot == 3) slot = 0;
    }

    // merge across the 4 lanes of each quad (different code columns)
#pragma unroll
    for (int k = 0; k < 4; ++k) {
#pragma unroll
        for (int off = 1; off <= 2; off <<= 1) {
            float ob = __shfl_xor_sync(0xffffffffu, tb[k], off);
            float os = __shfl_xor_sync(0xffffffffu, ts[k], off);
            int   oi = __shfl_xor_sync(0xffffffffu, tix[k], off);
            if (ob > tb[k]) { ts[k] = fmaxf(tb[k], os); tb[k] = ob; tix[k] = oi; }
            else if (ob == tb[k]) { ts[k] = tb[k]; if (oi < tix[k]) tix[k] = oi; }
            else { ts[k] = fmaxf(ts[k], ob); }
        }
    }

    __syncthreads();   // done with A/B smem; reuse for reduction
    float* rb = (float*)smem;          // [4][64]
    float* rs = rb + 256;              // [4][64]
    int*   ri = (int*)(rs + 256);      // [4][64]
    if ((lane & 3) == 0) {
#pragma unroll
        for (int k = 0; k < 4; ++k) {
            int tl = wm * 32 + (k >> 1) * 16 + (lane >> 2) + (k & 1) * 8;
            rb[wn * 64 + tl] = tb[k];
            rs[wn * 64 + tl] = ts[k];
            ri[wn * 64 + tl] = tix[k];
        }
    }
    __syncthreads();
    if (tid < 64) {
        float b = rb[tid], s = rs[tid]; int i = ri[tid];
#pragma unroll
        for (int w = 1; w < 4; ++w) {
            float ob = rb[w * 64 + tid], os = rs[w * 64 + tid];
            int oi = ri[w * 64 + tid];
            if (ob > b) { s = fmaxf(b, os); b = ob; i = oi; }
            else if (ob == b) { s = b; if (oi < i) i = oi; }
            else { s = fmaxf(s, ob); }
        }
        int tok = t0g + tid;
        g_code[tok] = i;
        int fl = (b - s < TAU) ? 1 : 0;
        g_flag[tok] = fl;
        if (fl) {
            g_best64[tok] = 0ull;
            int p = atomicAdd(&g_qn, 1);
            g_queue[p] = tok;
        }
    }
}

// ---------------- Kernel 4: throughput rescore (exact fp32 mini-GEMM) -----
// 64-code tiles (staging-optimal), grid (128 slices x 4 token-tile rows).
__global__ void __launch_bounds__(256, 1)
vq_rescore(const float* __restrict__ x, const float* __restrict__ w) {
    extern __shared__ float rsm[];
    float* cs = rsm;                 // [64][260]
    float* xs = rsm + RS_CS_F;       // [256][33]
    int tid = threadIdx.x, lane = tid & 31, wrp = tid >> 5;
    int qn = g_qn;
    if (qn == 0) return;
    if ((int)blockIdx.y * 32 >= qn) return;

    int code0 = blockIdx.x << 6;
#pragma unroll
    for (int i = 0; i < 16; ++i) {
        int g = i * 256 + tid;
        int code = g >> 6, q = g & 63;
        ((float4*)(cs + code * 260))[q] =
            *(const float4*)(w + (size_t)(code0 + code) * 256 + q * 4);
    }
    float hn8[8];
#pragma unroll
    for (int c8 = 0; c8 < 8; ++c8) hn8[c8] = g_hn[code0 + wrp * 8 + c8];

    for (int tile = blockIdx.y; tile * 32 < qn; tile += (int)gridDim.y) {
        int tbase = tile * 32;
        int ntok = min(32, qn - tbase);
        __syncthreads();
#pragma unroll
        for (int i = 0; i < 32; ++i) {
            int g = i * 256 + tid;
            int c = g >> 5, tok = g & 31;
            if (tok < ntok) {
                int t = g_queue[tbase + tok];
                int b = t >> 10, hw = t & 1023;
                xs[c * 33 + tok] = x[((size_t)b * 256 + c) * 1024 + hw];
            }
        }
        __syncthreads();

        int myoff = (lane < ntok) ? lane : 0;
        float acc[8];
#pragma unroll
        for (int c8 = 0; c8 < 8; ++c8) acc[c8] = 0.f;
#pragma unroll
        for (int kc = 0; kc < 16; ++kc) {
            float xr[16];
#pragma unroll
            for (int j = 0; j < 16; ++j) xr[j] = xs[(kc * 16 + j) * 33 + myoff];
#pragma unroll
            for (int c8 = 0; c8 < 8; ++c8) {
                const float4* cr = (const float4*)(cs + (wrp * 8 + c8) * 260 + kc * 16);
#pragma unroll
                for (int v = 0; v < 4; ++v) {
                    float4 cv = cr[v];
                    acc[c8] = fmaf(xr[v * 4 + 0], cv.x, acc[c8]);
                    acc[c8] = fmaf(xr[v * 4 + 1], cv.y, acc[c8]);
                    acc[c8] = fmaf(xr[v * 4 + 2], cv.z, acc[c8]);
                    acc[c8] = fmaf(xr[v * 4 + 3], cv.w, acc[c8]);
                }
            }
        }
        float best = acc[0] - hn8[0]; int bi = code0 + wrp * 8;
#pragma unroll
        for (int c8 = 1; c8 < 8; ++c8) {
            float v = acc[c8] - hn8[c8];
            if (v > best) { best = v; bi = code0 + wrp * 8 + c8; }
        }
        if (lane < ntok) {
            int t = g_queue[tbase + lane];
            atomicMax(&g_best64[t], pack_si(best, bi));
        }
    }
}

// ---------------- Kernel 5: gather x_q + code output + loss partials ------
__global__ void vq_gather(const float* __restrict__ x, const float* __restrict__ w,
                          float* __restrict__ out) {
    int bx = blockIdx.x;
    int b = bx >> 5, hw0 = (bx & 31) << 5;
    int tid = threadIdx.x;
    int hwl = tid & 31, cg = tid >> 5;
    int t = b * HW_ + hw0 + hwl;
    int k;
    if (g_flag[t]) {
        k = unpack_idx(g_best64[t]);
    } else {
        k = g_code[t];
    }
    if (cg == 0) out[CODE_OFF + t] = (float)k;   // code output (token-major == B,H,W)
    const float* e  = w + (size_t)k * C_;
    const float* xb = x + (size_t)b * (C_ * HW_) + hw0 + hwl;
    float* ob = out + (size_t)b * (C_ * HW_) + hw0 + hwl;
    float ls = 0.f;
#pragma unroll
    for (int p = 0; p < 8; ++p) {
        int c0 = ((p << 3) + cg) << 2;
        float4 ev = *(const float4*)(e + c0);
#pragma unroll
        for (int j = 0; j < 4; ++j) {
            int c = c0 + j;
            float v  = f4get(ev, j);
            float xv = xb[(size_t)c * HW_];
            ob[(size_t)c * HW_] = v;
            float dd = v - xv;
            ls += dd * dd;
        }
    }
#pragma unroll
    for (int off = 16; off > 0; off >>= 1)
        ls += __shfl_down_sync(0xffffffffu, ls, off);
    __shared__ float ws[8];
    if ((tid & 31) == 0) ws[tid >> 5] = ls;
    __syncthreads();
    if (tid == 0) {
        float s = 0.f;
#pragma unroll
        for (int i = 0; i < 8; ++i) s += ws[i];
        g_partial[bx] = (double)s;
    }
}

// ---------------- Kernel 6: finalize loss ----------------
__global__ void vq_finalize(float* __restrict__ out) {
    if (threadIdx.x == 0) {
        double s = 0.0;
        for (int i = 0; i < 512; ++i) s += g_partial[i];
        out[LOSS_OFF] = (float)(1.25 * s / (double)XQ_SIZE);
    }
}

// ---------------- Launch ----------------
extern "C" void kernel_launch(void* const* d_in, const int* in_sizes, int n_in,
                              void* d_out, int out_size) {
    const float* x = (const float*)d_in[0];
    const float* w = (const float*)d_in[1];
    float* out = (float*)d_out;

    cudaFuncSetAttribute((const void*)vq_argmax_mma,
                         cudaFuncAttributeMaxDynamicSharedMemorySize, SMEM_TOTAL);
    cudaFuncSetAttribute((const void*)vq_rescore,
                         cudaFuncAttributeMaxDynamicSharedMemorySize, RS_SMEM);

    vq_prep<<<dim3(8, 32, 16), dim3(32, 8)>>>(x);
    vq_wprep<<<KCODE, 256>>>(w);
    vq_argmax_mma<<<256, 256, SMEM_TOTAL>>>();
    vq_rescore<<<dim3(128, 4), 256, RS_SMEM>>>(x, w);
    vq_gather<<<512, 256>>>(x, w, out);
    vq_finalize<<<1, 32>>>(out);
}

// round 15
// speedup vs baseline: 1.3533x; 1.0730x over previous
#include <cuda_runtime.h>
#include <cuda_fp16.h>
#include <math_constants.h>
#include <cstdint>

#define B_    16
#define C_    256
#define HW_   1024
#define NTOK  16384
#define KCODE 8192
#define XQ_SIZE  4194304
#define LOSS_OFF 4194304
#define CODE_OFF 4194305
#define TAU   2e-3f

// A: 64 rows x 512B (256 fp16) + 16 pad = 528B pitch
#define A_PITCH   528
#define A_BYTES   (64 * A_PITCH)             // 33792
// B stage: 256 codes x 64B (32 fp16) + 16 pad = 80B pitch, 3-stage ring
#define B_PITCH   80
#define B_STAGE   (256 * B_PITCH)            // 20480
#define B_OFF     A_BYTES
#define HN_OFF    (A_BYTES + 3 * B_STAGE)    // 95232
#define SMEM_TOTAL (HN_OFF + 2048)           // 97280  (2 CTAs/SM)

// rescore smem: cs[64][260] + xsT[256][33]  (floats)
#define RS_CS_F   (64 * 260)                 // 16640
#define RS_XS_F   (256 * 33)                 // 8448
#define RS_SMEM   ((RS_CS_F + RS_XS_F) * 4)  // 100352

// ---------------- Device scratch ----------------
__device__ __align__(256) __half g_A[NTOK * 256];    // xh per token
__device__ __align__(256) __half g_Bw[KCODE * 256];  // eh per code
__device__ __align__(256) float g_hn[KCODE];
__device__ __align__(256) float g_xq[NTOK * 256];    // compact flagged-x buffer
__device__ int    g_code[NTOK];
__device__ int    g_flag[NTOK];
__device__ int    g_qn;
__device__ int    g_queue[NTOK];
__device__ unsigned long long g_best64[NTOK];
__device__ double g_partial[512];

// ---------------- helpers ----------------
__device__ __forceinline__ uint32_t smem_u32(const void* p) {
    uint32_t a;
    asm("{ .reg .u64 t; cvta.to.shared.u64 t, %1; cvt.u32.u64 %0, t; }" : "=r"(a) : "l"(p));
    return a;
}
__device__ __forceinline__ void cp_async16(uint32_t dst, const void* src) {
    asm volatile("cp.async.cg.shared.global [%0], [%1], 16;" :: "r"(dst), "l"(src) : "memory");
}
#define CP_COMMIT() asm volatile("cp.async.commit_group;" ::: "memory")
#define CP_WAIT(n)  asm volatile("cp.async.wait_group %0;" :: "n"(n) : "memory")

__device__ __forceinline__ void ldsm4(uint32_t* r, uint32_t addr) {
    asm volatile("ldmatrix.sync.aligned.m8n8.x4.shared.b16 {%0,%1,%2,%3}, [%4];"
                 : "=r"(r[0]), "=r"(r[1]), "=r"(r[2]), "=r"(r[3]) : "r"(addr));
}
__device__ __forceinline__ void mma_fp16(float* d, const uint32_t* a, const uint32_t* b) {
    asm volatile("mma.sync.aligned.m16n8k16.row.col.f32.f16.f16.f32 "
                 "{%0,%1,%2,%3}, {%4,%5,%6,%7}, {%8,%9}, {%0,%1,%2,%3};"
                 : "+f"(d[0]), "+f"(d[1]), "+f"(d[2]), "+f"(d[3])
                 : "r"(a[0]), "r"(a[1]), "r"(a[2]), "r"(a[3]), "r"(b[0]), "r"(b[1]));
}
__device__ __forceinline__ float f4get(const float4& v, int q) {
    switch (q) { case 0: return v.x; case 1: return v.y; case 2: return v.z; default: return v.w; }
}
__device__ __forceinline__ void upd(float& b, float& s, int& i, float v, int c) {
    if (v > b) { s = b; b = v; i = c; }
    else if (v > s) s = v;
}
// order-preserving (score, idx) pack: higher score wins; ties -> smaller idx.
__device__ __forceinline__ unsigned long long pack_si(float s, int idx) {
    uint32_t u = __float_as_uint(s);
    u = (u & 0x80000000u) ? ~u : (u | 0x80000000u);
    return ((unsigned long long)u << 32) | (uint32_t)(0xFFFFFFFFu - (uint32_t)idx);
}
__device__ __forceinline__ int unpack_idx(unsigned long long k) {
    return (int)(0xFFFFFFFFu - (uint32_t)(k & 0xFFFFFFFFull));
}

// ---------------- Kernel 1: x -> token-major fp16 ----------------
__global__ void vq_prep(const float* __restrict__ x) {
    __shared__ float tile[32][33];
    int c0 = blockIdx.x << 5, hw0 = blockIdx.y << 5, b = blockIdx.z;
    const float* xb = x + (size_t)b * (C_ * HW_);
#pragma unroll
    for (int k = 0; k < 4; ++k)
        tile[threadIdx.y + k * 8][threadIdx.x] =
            xb[(size_t)(c0 + threadIdx.y + k * 8) * HW_ + hw0 + threadIdx.x];
    __syncthreads();
#pragma unroll
    for (int k = 0; k < 4; ++k) {
        int token = b * HW_ + hw0 + threadIdx.y + k * 8;
        int c = c0 + threadIdx.x;
        g_A[(size_t)token * 256 + c] = __float2half_rn(tile[threadIdx.x][threadIdx.y + k * 8]);
    }
}

// ---------------- Kernel 2: w -> fp16 eh + hn + queue reset ----------
__global__ void vq_wprep(const float* __restrict__ w) {
    int k = blockIdx.x, c = threadIdx.x;
    if (k == 0 && c == 0) g_qn = 0;
    float e = w[(size_t)k * C_ + c];
    g_Bw[(size_t)k * 256 + c] = __float2half_rn(e);
    float s = e * e;
#pragma unroll
    for (int off = 16; off > 0; off >>= 1)
        s += __shfl_down_sync(0xffffffffu, s, off);
    __shared__ float ws[8];
    if ((c & 31) == 0) ws[c >> 5] = s;
    __syncthreads();
    if (c == 0) {
        float t = 0.f;
#pragma unroll
        for (int i = 0; i < 8; ++i) t += ws[i];
        g_hn[k] = 0.5f * t;
    }
}

// ---------------- Kernel 3: fp16 HMMA GEMM + fused argmax ----------------
// 256 CTAs x 64 tokens, 2 CTAs/SM. score = xh.eh (err ~2e-4 RMS, TAU=2e-3).
// 256 gstages = 32 chunks (256 codes) x 8 k-slabs (32 k). 3-stage cp.async ring.
__device__ __forceinline__ void issue_stage(uint32_t sb, int slot, int gs, int tid) {
    int ch = gs >> 3, kc = gs & 7;
    const __half* src = g_Bw + (size_t)ch * (256 * 256) + kc * 32;
    uint32_t dst = sb + B_OFF + slot * B_STAGE;
#pragma unroll
    for (int i = 0; i < 4; ++i) {
        int g = i * 256 + tid;          // 1024 granules of 16B (256 codes x 4)
        int code = g >> 2, q = g & 3;
        cp_async16(dst + code * B_PITCH + q * 16, src + (size_t)code * 256 + q * 8);
    }
}

__global__ void __launch_bounds__(256, 2) vq_argmax_mma() {
    extern __shared__ char smem[];
    uint32_t sb = smem_u32(smem);
    int tid = threadIdx.x, lane = tid & 31, wid = tid >> 5;
    int wm = wid >> 2, wn = wid & 3;
    int t0g = blockIdx.x << 6;

    // Prologue: A tile (64x512B) + stage0 + hn(chunk0); then stage1
#pragma unroll
    for (int i = 0; i < 8; ++i) {
        int g = i * 256 + tid;
        int row = g >> 5, q = g & 31;
        cp_async16(sb + row * A_PITCH + q * 16, g_A + (size_t)(t0g + row) * 256 + q * 8);
    }
    issue_stage(sb, 0, 0, tid);
    if (tid < 64) cp_async16(sb + HN_OFF + tid * 16, g_hn + tid * 4);
    CP_COMMIT();
    issue_stage(sb, 1, 1, tid);
    CP_COMMIT();

    uint32_t a_base = sb + (wm * 32 + (lane & 15)) * A_PITCH + (lane >> 4) * 16;
    uint32_t b_base = B_OFF +
        (uint32_t)(wn * 64 + ((lane >> 4) & 1) * 8 + (lane & 7)) * B_PITCH +
        ((lane >> 3) & 1) * 16;

    float tb[4], ts[4]; int tix[4];
#pragma unroll
    for (int k = 0; k < 4; ++k) { tb[k] = -CUDART_INF_F; ts[k] = -CUDART_INF_F; tix[k] = 0x7fffffff; }

    float d[2][8][4];
    int slot = 0;   // gs % 3

    for (int gs = 0; gs < 256; ++gs) {
        int ch = gs >> 3, kc = gs & 7;
        if (kc == 0) {
#pragma unroll
            for (int mt = 0; mt < 2; ++mt)
#pragma unroll
                for (int nt = 0; nt < 8; ++nt)
#pragma unroll
                    for (int q = 0; q < 4; ++q) d[mt][nt][q] = 0.f;
        }

        CP_WAIT(1);
        __syncthreads();
        uint32_t bst = sb + slot * B_STAGE + b_base;
        uint32_t ak = a_base + (uint32_t)(kc * 64);
#pragma unroll
        for (int j = 0; j < 2; ++j) {
            uint32_t ar[2][4];
#pragma unroll
            for (int mt = 0; mt < 2; ++mt)
                ldsm4(ar[mt], ak + mt * (16 * A_PITCH) + j * 32);
            uint32_t br[8][2];
#pragma unroll
            for (int p = 0; p < 4; ++p) {
                uint32_t r[4];
                ldsm4(r, bst + p * (16 * B_PITCH) + j * 32);
                br[2 * p][0] = r[0]; br[2 * p][1] = r[1];
                br[2 * p + 1][0] = r[2]; br[2 * p + 1][1] = r[3];
            }
#pragma unroll
            for (int mt = 0; mt < 2; ++mt)
#pragma unroll
                for (int nt = 0; nt < 8; ++nt)
                    mma_fp16(d[mt][nt], ar[mt], br[nt]);
        }
        // next issue targets slot (gs+2)%3, distinct from slots read at gs, gs+1;
        // the overwritten slot was last read at gs-1, sealed by the barrier above.
        int g2 = gs + 2;
        if (g2 < 256) {
            int slot2 = slot + 2; if (slot2 >= 3) slot2 -= 3;
            issue_stage(sb, slot2, g2, tid);
            if (kc == 0 && tid < 64 && ch + 1 < 32) {
                int ch2 = ch + 1;
                cp_async16(sb + HN_OFF + ((ch2 & 1) << 10) + tid * 16,
                           g_hn + ch2 * 256 + tid * 4);
            }
            CP_COMMIT();
        }

        if (kc == 7) {
            const float* hnc = (const float*)(smem + HN_OFF + ((ch & 1) << 10));
            int n0 = ch * 256 + wn * 64 + (lane & 3) * 2;
            int l0 = wn * 64 + (lane & 3) * 2;
#pragma unroll
            for (int mt = 0; mt < 2; ++mt) {
#pragma unroll
                for (int nt = 0; nt < 8; ++nt) {
                    int c0 = n0 + nt * 8;
                    float2 h = *(const float2*)(hnc + l0 + nt * 8);
                    upd(tb[2 * mt], ts[2 * mt], tix[2 * mt], d[mt][nt][0] - h.x, c0);
                    upd(tb[2 * mt], ts[2 * mt], tix[2 * mt], d[mt][nt][1] - h.y, c0 + 1);
                    upd(tb[2 * mt + 1], ts[2 * mt + 1], tix[2 * mt + 1], d[mt][nt][2] - h.x, c0);
                    upd(tb[2 * mt + 1], ts[2 * mt + 1], tix[2 * mt + 1], d[mt][nt][3] - h.y, c0 + 1);
                }
            }
        }
        if (++slot == 3) slot = 0;
    }

    // merge across the 4 lanes of each quad (different code columns)
#pragma unroll
    for (int k = 0; k < 4; ++k) {
#pragma unroll
        for (int off = 1; off <= 2; off <<= 1) {
            float ob = __shfl_xor_sync(0xffffffffu, tb[k], off);
            float os = __shfl_xor_sync(0xffffffffu, ts[k], off);
            int   oi = __shfl_xor_sync(0xffffffffu, tix[k], off);
            if (ob > tb[k]) { ts[k] = fmaxf(tb[k], os); tb[k] = ob; tix[k] = oi; }
            else if (ob == tb[k]) { ts[k] = tb[k]; if (oi < tix[k]) tix[k] = oi; }
            else { ts[k] = fmaxf(ts[k], ob); }
        }
    }

    __syncthreads();   // done with A/B smem; reuse for reduction
    float* rb = (float*)smem;          // [4][64]
    float* rs = rb + 256;              // [4][64]
    int*   ri = (int*)(rs + 256);      // [4][64]
    if ((lane & 3) == 0) {
#pragma unroll
        for (int k = 0; k < 4; ++k) {
            int tl = wm * 32 + (k >> 1) * 16 + (lane >> 2) + (k & 1) * 8;
            rb[wn * 64 + tl] = tb[k];
            rs[wn * 64 + tl] = ts[k];
            ri[wn * 64 + tl] = tix[k];
        }
    }
    __syncthreads();
    if (tid < 64) {
        float b = rb[tid], s = rs[tid]; int i = ri[tid];
#pragma unroll
        for (int w = 1; w < 4; ++w) {
            float ob = rb[w * 64 + tid], os = rs[w * 64 + tid];
            int oi = ri[w * 64 + tid];
            if (ob > b) { s = fmaxf(b, os); b = ob; i = oi; }
            else if (ob == b) { s = b; if (oi < i) i = oi; }
            else { s = fmaxf(s, ob); }
        }
        int tok = t0g + tid;
        g_code[tok] = i;
        int fl = (b - s < TAU) ? 1 : 0;
        g_flag[tok] = fl;
        if (fl) {
            g_best64[tok] = 0ull;
            int p = atomicAdd(&g_qn, 1);
            g_queue[p] = tok;
        }
    }
}

// ---------------- Kernel 3b: gather flagged x into compact buffer ---------
// One warp per queue entry; strided reads happen ONCE (instead of per-slice).
__global__ void vq_qprep(const float* __restrict__ x) {
    int qn = g_qn;
    int wrp = (blockIdx.x * blockDim.x + threadIdx.x) >> 5;
    int lane = threadIdx.x & 31;
    int nw = (gridDim.x * blockDim.x) >> 5;
    for (int qi = wrp; qi < qn; qi += nw) {
        int t = g_queue[qi];
        int b = t >> 10, hw = t & 1023;
        const float* xb = x + (size_t)b * (C_ * HW_) + hw;
        float* dst = g_xq + (size_t)qi * 256;
#pragma unroll
        for (int i = 0; i < 8; ++i) {
            int c = i * 32 + lane;
            dst[c] = xb[(size_t)c * HW_];
        }
    }
}

// ---------------- Kernel 4: throughput rescore (exact fp32 mini-GEMM) -----
// 64-code tiles; x read coalesced from compact g_xq.
__global__ void __launch_bounds__(256, 1)
vq_rescore(const float* __restrict__ w) {
    extern __shared__ float rsm[];
    float* cs = rsm;                 // [64][260]
    float* xs = rsm + RS_CS_F;       // [256][33]
    int tid = threadIdx.x, lane = tid & 31, wrp = tid >> 5;
    int qn = g_qn;
    if (qn == 0) return;
    if ((int)blockIdx.y * 32 >= qn) return;

    int code0 = blockIdx.x << 6;
#pragma unroll
    for (int i = 0; i < 16; ++i) {
        int g = i * 256 + tid;
        int code = g >> 6, q = g & 63;
        ((float4*)(cs + code * 260))[q] =
            *(const float4*)(w + (size_t)(code0 + code) * 256 + q * 4);
    }
    float hn8[8];
#pragma unroll
    for (int c8 = 0; c8 < 8; ++c8) hn8[c8] = g_hn[code0 + wrp * 8 + c8];

    for (int tile = blockIdx.y; tile * 32 < qn; tile += (int)gridDim.y) {
        int tbase = tile * 32;
        int ntok = min(32, qn - tbase);
        __syncthreads();
        // coalesced float4 loads from compact buffer, scatter to xs[c*33+tok]
#pragma unroll
        for (int i = 0; i < 8; ++i) {
            int g = i * 256 + tid;       // 2048 float4 granules
            int tok = g >> 6, q = g & 63;
            if (tok < ntok) {
                float4 v = *(const float4*)(g_xq + (size_t)(tbase + tok) * 256 + q * 4);
                xs[(q * 4 + 0) * 33 + tok] = v.x;
                xs[(q * 4 + 1) * 33 + tok] = v.y;
                xs[(q * 4 + 2) * 33 + tok] = v.z;
                xs[(q * 4 + 3) * 33 + tok] = v.w;
            }
        }
        __syncthreads();

        int myoff = (lane < ntok) ? lane : 0;
        float acc[8];
#pragma unroll
        for (int c8 = 0; c8 < 8; ++c8) acc[c8] = 0.f;
#pragma unroll
        for (int kc = 0; kc < 16; ++kc) {
            float xr[16];
#pragma unroll
            for (int j = 0; j < 16; ++j) xr[j] = xs[(kc * 16 + j) * 33 + myoff];
#pragma unroll
            for (int c8 = 0; c8 < 8; ++c8) {
                const float4* cr = (const float4*)(cs + (wrp * 8 + c8) * 260 + kc * 16);
#pragma unroll
                for (int v = 0; v < 4; ++v) {
                    float4 cv = cr[v];
                    acc[c8] = fmaf(xr[v * 4 + 0], cv.x, acc[c8]);
                    acc[c8] = fmaf(xr[v * 4 + 1], cv.y, acc[c8]);
                    acc[c8] = fmaf(xr[v * 4 + 2], cv.z, acc[c8]);
                    acc[c8] = fmaf(xr[v * 4 + 3], cv.w, acc[c8]);
                }
            }
        }
        float best = acc[0] - hn8[0]; int bi = code0 + wrp * 8;
#pragma unroll
        for (int c8 = 1; c8 < 8; ++c8) {
            float v = acc[c8] - hn8[c8];
            if (v > best) { best = v; bi = code0 + wrp * 8 + c8; }
        }
        if (lane < ntok) {
            int t = g_queue[tbase + lane];
            atomicMax(&g_best64[t], pack_si(best, bi));
        }
    }
}

// ---------------- Kernel 5: gather x_q + code output + loss partials ------
__global__ void vq_gather(const float* __restrict__ x, const float* __restrict__ w,
                          float* __restrict__ out) {
    int bx = blockIdx.x;
    int b = bx >> 5, hw0 = (bx & 31) << 5;
    int tid = threadIdx.x;
    int hwl = tid & 31, cg = tid >> 5;
    int t = b * HW_ + hw0 + hwl;
    int k;
    if (g_flag[t]) {
        k = unpack_idx(g_best64[t]);
    } else {
        k = g_code[t];
    }
    if (cg == 0) out[CODE_OFF + t] = (float)k;   // code output (token-major == B,H,W)
    const float* e  = w + (size_t)k * C_;
    const float* xb = x + (size_t)b * (C_ * HW_) + hw0 + hwl;
    float* ob = out + (size_t)b * (C_ * HW_) + hw0 + hwl;
    float ls = 0.f;
#pragma unroll
    for (int p = 0; p < 8; ++p) {
        int c0 = ((p << 3) + cg) << 2;
        float4 ev = *(const float4*)(e + c0);
#pragma unroll
        for (int j = 0; j < 4; ++j) {
            int c = c0 + j;
            float v  = f4get(ev, j);
            float xv = xb[(size_t)c * HW_];
            ob[(size_t)c * HW_] = v;
            float dd = v - xv;
            ls += dd * dd;
        }
    }
#pragma unroll
    for (int off = 16; off > 0; off >>= 1)
        ls += __shfl_down_sync(0xffffffffu, ls, off);
    __shared__ float ws[8];
    if ((tid & 31) == 0) ws[tid >> 5] = ls;
    __syncthreads();
    if (tid == 0) {
        float s = 0.f;
#pragma unroll
        for (int i = 0; i < 8; ++i) s += ws[i];
        g_partial[bx] = (double)s;
    }
}

// ---------------- Kernel 6: finalize loss ----------------
__global__ void vq_finalize(float* __restrict__ out) {
    if (threadIdx.x == 0) {
        double s = 0.0;
        for (int i = 0; i < 512; ++i) s += g_partial[i];
        out[LOSS_OFF] = (float)(1.25 * s / (double)XQ_SIZE);
    }
}

// ---------------- Launch ----------------
extern "C" void kernel_launch(void* const* d_in, const int* in_sizes, int n_in,
                              void* d_out, int out_size) {
    const float* x = (const float*)d_in[0];
    const float* w = (const float*)d_in[1];
    float* out = (float*)d_out;

    cudaFuncSetAttribute((const void*)vq_argmax_mma,
                         cudaFuncAttributeMaxDynamicSharedMemorySize, SMEM_TOTAL);
    cudaFuncSetAttribute((const void*)vq_rescore,
                         cudaFuncAttributeMaxDynamicSharedMemorySize, RS_SMEM);

    vq_prep<<<dim3(8, 32, 16), dim3(32, 8)>>>(x);
    vq_wprep<<<KCODE, 256>>>(w);
    vq_argmax_mma<<<256, 256, SMEM_TOTAL>>>();
    vq_qprep<<<64, 256>>>(x);
    vq_rescore<<<dim3(128, 4), 256, RS_SMEM>>>(w);
    vq_gather<<<512, 256>>>(x, w, out);
    vq_finalize<<<1, 32>>>(out);
}